// round 7
// baseline (speedup 1.0000x reference)
#include <cuda_runtime.h>
#include <math.h>

// Problem constants (hard-coded in reference)
#define SGRID   7
#define CELLS   49          // 7*7
#define CH      30
#define BATCH   16384
#define NCELL   (BATCH * CELLS)   // 802816
#define CELLPX  64.0f
#define IMGPX   448.0f

__global__ void yolo_zero_kernel(float* out) { out[0] = 0.0f; }

// Axis-aligned IoU of two decoded+clipped boxes given as corner coords.
__device__ __forceinline__ float iou_corners(
    float ax1, float ay1, float ax2, float ay2,
    float bx1, float by1, float bx2, float by2)
{
    float l  = fmaxf(ax1, bx1);
    float r  = fminf(ax2, bx2);
    float t  = fmaxf(ay1, by1);
    float bo = fminf(ay2, by2);
    bool  m  = (l < r) && (t < bo);
    float inter = (r - l) * (bo - t);
    float uni   = (ax2 - ax1) * (ay2 - ay1) + (bx2 - bx1) * (by2 - by1);
    float denom = uni - inter;
    return m ? (inter / denom) : 0.0f;
}

// Decode a 5-channel box (cx,cy,w,h,conf prefix) into clipped corners.
__device__ __forceinline__ void decode_box(
    float pcx, float pcy, float pw, float ph, float gx, float gy,
    float& x1, float& y1, float& x2, float& y2)
{
    float cx = fmaf(pcx, CELLPX, gx);
    float cy = fmaf(pcy, CELLPX, gy);
    float w  = pw * IMGPX;
    float h  = ph * IMGPX;
    x1 = fminf(fmaxf(cx - 0.5f * w, 0.0f), IMGPX);
    y1 = fminf(fmaxf(cy - 0.5f * h, 0.0f), IMGPX);
    x2 = fminf(fmaxf(cx + 0.5f * w, 0.0f), IMGPX);
    y2 = fminf(fmaxf(cy + 0.5f * h, 0.0f), IMGPX);
}

__global__ __launch_bounds__(256, 4)
void yolo_loss_kernel(const float* __restrict__ in,   // [B,30,7,7]
                      const float* __restrict__ tgt,  // [B,7,7,30]
                      float* __restrict__ out)
{
    const int gid = blockIdx.x * blockDim.x + threadIdx.x;

    float loss = 0.0f;
    if (gid < NCELL) {
        const int b    = gid / CELLS;
        const int cell = gid - b * CELLS;
        const int row  = cell / SGRID;
        const int col  = cell - row * SGRID;
        const float gx = (float)col * CELLPX;
        const float gy = (float)row * CELLPX;

        // ---- target row: 30 contiguous f32, 8B aligned -> 15 x float2 ----
        float t[CH];
        {
            const float2* tp2 = reinterpret_cast<const float2*>(tgt + (size_t)gid * CH);
            #pragma unroll
            for (int i = 0; i < CH / 2; i++) {
                float2 v = __ldg(tp2 + i);
                t[2 * i]     = v.x;
                t[2 * i + 1] = v.y;
            }
        }

        // ---- prediction: channel-strided (stride 49 floats), coalesced across warp ----
        const float* ip = in + (size_t)b * (CH * CELLS) + cell;
        float x[10];
        #pragma unroll
        for (int c = 0; c < 10; c++) x[c] = __ldg(ip + c * CELLS);

        // class term computed streaming (keeps regs low)
        float cls = 0.0f;
        #pragma unroll
        for (int c = 10; c < CH; c++) {
            float d = __ldg(ip + c * CELLS) - t[c];
            cls = fmaf(d, d, cls);
        }

        // ---- decode 4 boxes, 2 IoUs ----
        float px1, py1, px2, py2, qx1, qy1, qx2, qy2;
        float tx1, ty1, tx2, ty2, ux1, uy1, ux2, uy2;
        decode_box(x[0], x[1], x[2], x[3], gx, gy, px1, py1, px2, py2);
        decode_box(x[5], x[6], x[7], x[8], gx, gy, qx1, qy1, qx2, qy2);
        decode_box(t[0], t[1], t[2], t[3], gx, gy, tx1, ty1, tx2, ty2);
        decode_box(t[5], t[6], t[7], t[8], gx, gy, ux1, uy1, ux2, uy2);

        float iou1 = iou_corners(px1, py1, px2, py2, tx1, ty1, tx2, ty2);
        float iou2 = iou_corners(qx1, qy1, qx2, qy2, ux1, uy1, ux2, uy2);

        const bool mask = iou1 < iou2;           // strict, per reference
        const float iou = mask ? iou2 : iou1;
        const float s0 = mask ? x[5] : x[0];
        const float s1 = mask ? x[6] : x[1];
        const float s2 = mask ? x[7] : x[2];
        const float s3 = mask ? x[8] : x[3];
        const float s4 = mask ? x[9] : x[4];

        const float w = (t[4] == 1.0f) ? 1.0f : 0.0f;

        float d0 = s0 - t[0];
        float d1 = s1 - t[1];
        float coord = fmaf(d0, d0, d1 * d1);

        float e0 = sqrtf(s2) - sqrtf(t[2]);
        float e1 = sqrtf(s3) - sqrtf(t[3]);
        float size = fmaf(e0, e0, e1 * e1);

        float dc = s4 - iou;
        float conf  = dc * dc;
        float noobj = s4 * s4;

        loss = w * (5.0f * (coord + size) + conf + cls)
             + (1.0f - w) * 0.5f * noobj;
    }

    // ---- reduce: warp shuffle -> shared -> one atomicAdd per block ----
    #pragma unroll
    for (int off = 16; off > 0; off >>= 1)
        loss += __shfl_down_sync(0xFFFFFFFFu, loss, off);

    __shared__ float warp_sums[8];   // 256 threads = 8 warps
    const int lane = threadIdx.x & 31;
    const int wid  = threadIdx.x >> 5;
    if (lane == 0) warp_sums[wid] = loss;
    __syncthreads();

    if (wid == 0) {
        float v = (lane < 8) ? warp_sums[lane] : 0.0f;
        #pragma unroll
        for (int off = 4; off > 0; off >>= 1)
            v += __shfl_down_sync(0xFFFFFFFFu, v, off);
        if (lane == 0) atomicAdd(out, v);
    }
}

extern "C" void kernel_launch(void* const* d_in, const int* in_sizes, int n_in,
                              void* d_out, int out_size)
{
    const float* in  = (const float*)d_in[0];   // [B,30,7,7]
    const float* tgt = (const float*)d_in[1];   // [B,7,7,30]
    float* out = (float*)d_out;

    yolo_zero_kernel<<<1, 1>>>(out);
    const int threads = 256;
    const int blocks  = (NCELL + threads - 1) / threads;   // 3136
    yolo_loss_kernel<<<blocks, threads>>>(in, tgt, out);
}

// round 8
// speedup vs baseline: 1.1298x; 1.1298x over previous
#include <cuda_runtime.h>
#include <math.h>

// Problem constants (hard-coded in reference)
#define SGRID   7
#define CELLS   49          // 7*7
#define CH      30
#define BATCH   16384
#define NCELL   (BATCH * CELLS)   // 802816 = 3136 * 256 exactly
#define CELLPX  64.0f
#define IMGPX   448.0f

#define TPB     256
#define NBLK    (NCELL / TPB)           // 3136, exact
#define TILE_F4 ((TPB * CH) / 4)        // 1920 float4 per block tile

__global__ void yolo_zero_kernel(float* out) { out[0] = 0.0f; }

// Axis-aligned IoU of two decoded+clipped boxes given as corner coords.
__device__ __forceinline__ float iou_corners(
    float ax1, float ay1, float ax2, float ay2,
    float bx1, float by1, float bx2, float by2)
{
    float l  = fmaxf(ax1, bx1);
    float r  = fminf(ax2, bx2);
    float t  = fmaxf(ay1, by1);
    float bo = fminf(ay2, by2);
    bool  m  = (l < r) && (t < bo);
    float inter = (r - l) * (bo - t);
    float uni   = (ax2 - ax1) * (ay2 - ay1) + (bx2 - bx1) * (by2 - by1);
    float denom = uni - inter;
    return m ? (inter / denom) : 0.0f;
}

// Decode a 5-channel box (cx,cy,w,h) into clipped corner coords.
__device__ __forceinline__ void decode_box(
    float pcx, float pcy, float pw, float ph, float gx, float gy,
    float& x1, float& y1, float& x2, float& y2)
{
    float cx = fmaf(pcx, CELLPX, gx);
    float cy = fmaf(pcy, CELLPX, gy);
    float w  = pw * IMGPX;
    float h  = ph * IMGPX;
    x1 = fminf(fmaxf(cx - 0.5f * w, 0.0f), IMGPX);
    y1 = fminf(fmaxf(cy - 0.5f * h, 0.0f), IMGPX);
    x2 = fminf(fmaxf(cx + 0.5f * w, 0.0f), IMGPX);
    y2 = fminf(fmaxf(cy + 0.5f * h, 0.0f), IMGPX);
}

__global__ __launch_bounds__(TPB, 5)
void yolo_loss_kernel(const float* __restrict__ in,   // [B,30,7,7]
                      const float* __restrict__ tgt,  // [B,7,7,30]
                      float* __restrict__ out)
{
    __shared__ float st[TPB * CH];      // 30720 B target tile
    __shared__ float warp_sums[TPB / 32];

    const int blockBase = blockIdx.x * TPB;
    const int gid = blockBase + threadIdx.x;

    // ---- cooperative stage of the target tile: fully coalesced LDG.128 ----
    // Block slice is 256*30 floats, contiguous, 16B-aligned (blockBase*120B).
    {
        const float4* src = reinterpret_cast<const float4*>(tgt) +
                            (size_t)blockBase * (CH / 4) + (size_t)blockBase * 0; // base below
        // base in float4 units: blockBase * 30 / 4 = blockBase * 7.5 -> compute in floats
        src = reinterpret_cast<const float4*>(tgt + (size_t)blockBase * CH);
        float4* dst = reinterpret_cast<float4*>(st);
        #pragma unroll
        for (int i = 0; i < 8; i++) {
            int idx = threadIdx.x + TPB * i;
            if (idx < TILE_F4) dst[idx] = __ldg(src + idx);
        }
    }

    // ---- prediction loads (independent of smem; issue before the sync) ----
    const int b    = gid / CELLS;
    const int cell = gid - b * CELLS;
    const int row  = cell / SGRID;
    const int col  = cell - row * SGRID;
    const float gx = (float)col * CELLPX;
    const float gy = (float)row * CELLPX;

    const float* ip = in + (size_t)b * (CH * CELLS) + cell;
    float x[10];
    #pragma unroll
    for (int c = 0; c < 10; c++) x[c] = __ldg(ip + c * CELLS);

    __syncthreads();
    const float* t = st + threadIdx.x * CH;   // this thread's target row (LDS)

    // ---- class term: stream pred channels 10..29 vs smem target ----
    float cls = 0.0f;
    #pragma unroll
    for (int c = 10; c < CH; c++) {
        float d = __ldg(ip + c * CELLS) - t[c];
        cls = fmaf(d, d, cls);
    }

    // ---- decode 4 boxes, 2 IoUs ----
    float t0 = t[0], t1 = t[1], t2 = t[2], t3 = t[3], t4 = t[4];
    float t5 = t[5], t6 = t[6], t7 = t[7], t8 = t[8];

    float px1, py1, px2, py2, qx1, qy1, qx2, qy2;
    float tx1, ty1, tx2, ty2, ux1, uy1, ux2, uy2;
    decode_box(x[0], x[1], x[2], x[3], gx, gy, px1, py1, px2, py2);
    decode_box(x[5], x[6], x[7], x[8], gx, gy, qx1, qy1, qx2, qy2);
    decode_box(t0,   t1,   t2,   t3,   gx, gy, tx1, ty1, tx2, ty2);
    decode_box(t5,   t6,   t7,   t8,   gx, gy, ux1, uy1, ux2, uy2);

    float iou1 = iou_corners(px1, py1, px2, py2, tx1, ty1, tx2, ty2);
    float iou2 = iou_corners(qx1, qy1, qx2, qy2, ux1, uy1, ux2, uy2);

    const bool mask = iou1 < iou2;           // strict, per reference
    const float iou = mask ? iou2 : iou1;
    const float s0 = mask ? x[5] : x[0];
    const float s1 = mask ? x[6] : x[1];
    const float s2 = mask ? x[7] : x[2];
    const float s3 = mask ? x[8] : x[3];
    const float s4 = mask ? x[9] : x[4];

    const float w = (t4 == 1.0f) ? 1.0f : 0.0f;

    float d0 = s0 - t0;
    float d1 = s1 - t1;
    float coord = fmaf(d0, d0, d1 * d1);

    float e0 = sqrtf(s2) - sqrtf(t2);
    float e1 = sqrtf(s3) - sqrtf(t3);
    float size = fmaf(e0, e0, e1 * e1);

    float dc = s4 - iou;
    float conf  = dc * dc;
    float noobj = s4 * s4;

    float loss = w * (5.0f * (coord + size) + conf + cls)
               + (1.0f - w) * 0.5f * noobj;

    // ---- reduce: warp shuffle -> shared -> one atomicAdd per block ----
    #pragma unroll
    for (int off = 16; off > 0; off >>= 1)
        loss += __shfl_down_sync(0xFFFFFFFFu, loss, off);

    const int lane = threadIdx.x & 31;
    const int wid  = threadIdx.x >> 5;
    if (lane == 0) warp_sums[wid] = loss;
    __syncthreads();

    if (wid == 0) {
        float v = (lane < TPB / 32) ? warp_sums[lane] : 0.0f;
        #pragma unroll
        for (int off = 4; off > 0; off >>= 1)
            v += __shfl_down_sync(0xFFFFFFFFu, v, off);
        if (lane == 0) atomicAdd(out, v);
    }
}

extern "C" void kernel_launch(void* const* d_in, const int* in_sizes, int n_in,
                              void* d_out, int out_size)
{
    const float* in  = (const float*)d_in[0];   // [B,30,7,7]
    const float* tgt = (const float*)d_in[1];   // [B,7,7,30]
    float* out = (float*)d_out;

    yolo_zero_kernel<<<1, 1>>>(out);
    yolo_loss_kernel<<<NBLK, TPB>>>(in, tgt, out);
}